// round 14
// baseline (speedup 1.0000x reference)
#include <cuda_runtime.h>
#include <math.h>
#include <stdint.h>

// Problem constants
#define Bq  2
#define Sq  2048
#define Dq  1024
#define Hq  16
#define HDq 64

__device__ float g_qkv[(size_t)Bq * Sq * 3 * Dq];   // (B,S,3D), tf32-rounded
__device__ float g_vals[(size_t)Bq * Sq * Dq];      // (B,S,D)

// ---------------------------------------------------------------------------
// tf32 helpers
// ---------------------------------------------------------------------------
__device__ __forceinline__ uint32_t f2tf32(float x) {
    uint32_t r;
    asm("cvt.rna.tf32.f32 %0, %1;" : "=r"(r) : "f"(x));
    return r;
}
__device__ __forceinline__ float roundtf(float x) {
    return __uint_as_float(f2tf32(x));
}

__device__ __forceinline__ void mma_tf32(float c[4],
                                         uint32_t a0, uint32_t a1, uint32_t a2, uint32_t a3,
                                         uint32_t b0, uint32_t b1) {
    asm volatile(
        "mma.sync.aligned.m16n8k8.row.col.f32.tf32.tf32.f32 "
        "{%0,%1,%2,%3}, {%4,%5,%6,%7}, {%8,%9}, {%0,%1,%2,%3};"
        : "+f"(c[0]), "+f"(c[1]), "+f"(c[2]), "+f"(c[3])
        : "r"(a0), "r"(a1), "r"(a2), "r"(a3), "r"(b0), "r"(b1));
}

// ---------------------------------------------------------------------------
// tf32 GEMM: C[M,N] = A[M,K] @ W[N,K]^T + bias[N]
// Round-14: BK 32 -> 64 (barriers per K-loop halved: 64 -> 32).
// Same warp layout (8 warps 2x4, warp 64x32), same fragment addressing
// (pitch 68 = 4 mod 32, identical bank pattern to pitch 36), same k order
// per accumulator -> bit-identical numerics. smem 69632 B dynamic,
// 2 CTAs/SM enforced via __launch_bounds__(256, 2).
// ---------------------------------------------------------------------------
#define GP 68   // GEMM smem pitch (words)

template <bool ROUND>
__global__ void __launch_bounds__(256, 2)
gemm_tf32_nt_bias(int M, int N, int K,
                  const float* __restrict__ A,
                  const float* __restrict__ W,
                  const float* __restrict__ bias,
                  float* __restrict__ C)
{
    constexpr int BK = 64;
    extern __shared__ uint32_t gsm[];
    uint32_t* As = gsm;               // [128][GP]
    uint32_t* Ws = gsm + 128 * GP;    // [128][GP]

    const int tid  = threadIdx.x;
    const int lane = tid & 31;
    const int w    = tid >> 5;
    const int wr   = w >> 2;      // 0..1
    const int wc   = w & 3;       // 0..3
    const int m0   = blockIdx.y * 128;
    const int n0   = blockIdx.x * 128;

    const int g  = lane >> 2;     // groupID 0..7
    const int tq = lane & 3;      // threadID in quad 0..3

    float acc[4][4][4];
#pragma unroll
    for (int i = 0; i < 4; i++)
#pragma unroll
        for (int j = 0; j < 4; j++)
#pragma unroll
            for (int e = 0; e < 4; e++) acc[i][j][e] = 0.0f;

    // loader: row = tid>>2 (0..63) and +64; cols (tid&3)*16 + j*4
    const int lrow = tid >> 2;
    const int lcb  = (tid & 3) << 4;

    for (int k0 = 0; k0 < K; k0 += BK) {
#pragma unroll
        for (int rr = 0; rr < 2; rr++) {
            const int r = lrow + rr * 64;
#pragma unroll
            for (int j = 0; j < 4; j++) {
                const int c4 = lcb + j * 4;
                float4 av = *(const float4*)(A + (size_t)(m0 + r) * K + k0 + c4);
                As[r * GP + c4 + 0] = f2tf32(av.x); As[r * GP + c4 + 1] = f2tf32(av.y);
                As[r * GP + c4 + 2] = f2tf32(av.z); As[r * GP + c4 + 3] = f2tf32(av.w);
                float4 wv = *(const float4*)(W + (size_t)(n0 + r) * K + k0 + c4);
                Ws[r * GP + c4 + 0] = f2tf32(wv.x); Ws[r * GP + c4 + 1] = f2tf32(wv.y);
                Ws[r * GP + c4 + 2] = f2tf32(wv.z); Ws[r * GP + c4 + 3] = f2tf32(wv.w);
            }
        }
        __syncthreads();

#pragma unroll
        for (int ks = 0; ks < 8; ks++) {
            const int kk = ks * 8;
            uint32_t af[4][4];
#pragma unroll
            for (int mi = 0; mi < 4; mi++) {
                const int rb = wr * 64 + mi * 16;
                af[mi][0] = As[(rb + g    ) * GP + kk + tq    ];
                af[mi][1] = As[(rb + g + 8) * GP + kk + tq    ];
                af[mi][2] = As[(rb + g    ) * GP + kk + tq + 4];
                af[mi][3] = As[(rb + g + 8) * GP + kk + tq + 4];
            }
            uint32_t bf[4][2];
#pragma unroll
            for (int ni = 0; ni < 4; ni++) {
                const int cb = wc * 32 + ni * 8;
                bf[ni][0] = Ws[(cb + g) * GP + kk + tq    ];
                bf[ni][1] = Ws[(cb + g) * GP + kk + tq + 4];
            }
#pragma unroll
            for (int mi = 0; mi < 4; mi++)
#pragma unroll
                for (int ni = 0; ni < 4; ni++)
                    mma_tf32(acc[mi][ni],
                             af[mi][0], af[mi][1], af[mi][2], af[mi][3],
                             bf[ni][0], bf[ni][1]);
        }
        __syncthreads();
    }

#pragma unroll
    for (int mi = 0; mi < 4; mi++) {
        const int r0 = m0 + wr * 64 + mi * 16 + g;
#pragma unroll
        for (int ni = 0; ni < 4; ni++) {
            const int c = n0 + wc * 32 + ni * 8 + 2 * tq;
            const float b0v = bias[c], b1v = bias[c + 1];
            float2 o0, o1;
            if (ROUND) {
                o0 = make_float2(roundtf(acc[mi][ni][0] + b0v), roundtf(acc[mi][ni][1] + b1v));
                o1 = make_float2(roundtf(acc[mi][ni][2] + b0v), roundtf(acc[mi][ni][3] + b1v));
            } else {
                o0 = make_float2(acc[mi][ni][0] + b0v, acc[mi][ni][1] + b1v);
                o1 = make_float2(acc[mi][ni][2] + b0v, acc[mi][ni][3] + b1v);
            }
            *(float2*)(C + (size_t)r0 * N + c)       = o0;
            *(float2*)(C + (size_t)(r0 + 8) * N + c) = o1;
        }
    }
}

// ---------------------------------------------------------------------------
// Flash attention, tf32 (verbatim round-11 kernel — measured best, 637.4us
// total). Grid (S/64, H, B), 128 threads, 4 CTAs/SM, smem 53248 B.
// ---------------------------------------------------------------------------
#define QP 68
#define VP 72

__global__ void __launch_bounds__(128, 4)
flash_attn_tf32(const float* __restrict__ qkv,
                const float* __restrict__ mask,
                float* __restrict__ out)
{
    extern __shared__ uint32_t sm[];
    uint32_t* Qs = sm;                  // [64][QP]  (persistent)
    uint32_t* Ks = sm + 64 * QP;        // [64][QP]  (doubles as P after S-phase)
    uint32_t* Vs = sm + 2 * 64 * QP;    // [64][VP]

    const int tid  = threadIdx.x;
    const int lane = tid & 31;
    const int wid  = tid >> 5;     // 0..3 -> q rows [wid*16, +16)
    const int g    = lane >> 2;    // 0..7
    const int tq   = lane & 3;     // 0..3

    const int q0 = blockIdx.x * 64;
    const int h  = blockIdx.y;
    const int b  = blockIdx.z;
    const float scale = 0.125f;

    const uint32_t* base =
        (const uint32_t*)(qkv + (size_t)b * Sq * (3 * Dq) + (size_t)h * (3 * HDq));

    // Load Q tile (64 x 64), already tf32-rounded -> raw copy
#pragma unroll
    for (int rr = 0; rr < 8; rr++) {
        const int r  = (tid >> 4) + rr * 8;
        const int c4 = (tid & 15) << 2;
        uint4 v = *(const uint4*)(base + (size_t)(q0 + r) * (3 * Dq) + c4);
        *(uint4*)(Qs + r * QP + c4) = v;
    }

    float Oacc[8][4];
#pragma unroll
    for (int ni = 0; ni < 8; ni++)
#pragma unroll
        for (int e = 0; e < 4; e++) Oacc[ni][e] = 0.0f;
    float mrow0 = -INFINITY, mrow1 = -INFINITY;
    float lrow0 = 0.0f, lrow1 = 0.0f;

    const int r0 = wid * 16 + g;   // this thread's first q row (within tile)
    const int r1 = r0 + 8;

    for (int kt = 0; kt < Sq / 64; kt++) {
        const int k0t = kt * 64;
        __syncthreads();   // prev PV done reading Ks(P)/Vs; Q visible on 1st iter

        // Load K and V tiles (pre-rounded) -> raw uint4 copies
#pragma unroll
        for (int rr = 0; rr < 8; rr++) {
            const int r  = (tid >> 4) + rr * 8;
            const int c4 = (tid & 15) << 2;
            uint4 kv = *(const uint4*)(base + 64 + (size_t)(k0t + r) * (3 * Dq) + c4);
            *(uint4*)(Ks + r * QP + c4) = kv;
            uint4 vv = *(const uint4*)(base + 128 + (size_t)(k0t + r) * (3 * Dq) + c4);
            *(uint4*)(Vs + r * VP + c4) = vv;
        }
        __syncthreads();

        // S = Q K^T : warp computes 16 x 64 (8 n-tiles)
        float Sacc[8][4];
#pragma unroll
        for (int ni = 0; ni < 8; ni++)
#pragma unroll
            for (int e = 0; e < 4; e++) Sacc[ni][e] = 0.0f;

#pragma unroll
        for (int ks = 0; ks < 8; ks++) {
            const int kk = ks * 8;
            const int mb = wid * 16;
            uint32_t a0 = Qs[(mb + g)     * QP + kk + tq];
            uint32_t a1 = Qs[(mb + g + 8) * QP + kk + tq];
            uint32_t a2 = Qs[(mb + g)     * QP + kk + tq + 4];
            uint32_t a3 = Qs[(mb + g + 8) * QP + kk + tq + 4];
#pragma unroll
            for (int ni = 0; ni < 8; ni++) {
                const int nb = ni * 8;
                uint32_t b0 = Ks[(nb + g) * QP + kk + tq];
                uint32_t b1 = Ks[(nb + g) * QP + kk + tq + 4];
                mma_tf32(Sacc[ni], a0, a1, a2, a3, b0, b1);
            }
        }

        // scale + mask + online softmax (rows r0, r1; cols 8*ni + 2*tq {,+1})
        float p0[8][2], p1[8][2];
        float rmax0 = -INFINITY, rmax1 = -INFINITY;
#pragma unroll
        for (int ni = 0; ni < 8; ni++) {
            const int c = ni * 8 + 2 * tq;
            float2 mk0 = *(const float2*)(mask + (size_t)(q0 + r0) * Sq + k0t + c);
            float2 mk1 = *(const float2*)(mask + (size_t)(q0 + r1) * Sq + k0t + c);
            p0[ni][0] = Sacc[ni][0] * scale + mk0.x;
            p0[ni][1] = Sacc[ni][1] * scale + mk0.y;
            p1[ni][0] = Sacc[ni][2] * scale + mk1.x;
            p1[ni][1] = Sacc[ni][3] * scale + mk1.y;
            rmax0 = fmaxf(rmax0, fmaxf(p0[ni][0], p0[ni][1]));
            rmax1 = fmaxf(rmax1, fmaxf(p1[ni][0], p1[ni][1]));
        }
#pragma unroll
        for (int off = 1; off < 4; off <<= 1) {
            rmax0 = fmaxf(rmax0, __shfl_xor_sync(0xffffffffu, rmax0, off));
            rmax1 = fmaxf(rmax1, __shfl_xor_sync(0xffffffffu, rmax1, off));
        }
        const float mnew0 = fmaxf(mrow0, rmax0);
        const float mnew1 = fmaxf(mrow1, rmax1);
        const float alpha0 = __expf(mrow0 - mnew0);
        const float alpha1 = __expf(mrow1 - mnew1);
        float rs0 = 0.0f, rs1 = 0.0f;
#pragma unroll
        for (int ni = 0; ni < 8; ni++) {
            p0[ni][0] = __expf(p0[ni][0] - mnew0);
            p0[ni][1] = __expf(p0[ni][1] - mnew0);
            p1[ni][0] = __expf(p1[ni][0] - mnew1);
            p1[ni][1] = __expf(p1[ni][1] - mnew1);
            rs0 += p0[ni][0] + p0[ni][1];
            rs1 += p1[ni][0] + p1[ni][1];
        }
#pragma unroll
        for (int off = 1; off < 4; off <<= 1) {
            rs0 += __shfl_xor_sync(0xffffffffu, rs0, off);
            rs1 += __shfl_xor_sync(0xffffffffu, rs1, off);
        }
        lrow0 = lrow0 * alpha0 + rs0;
        lrow1 = lrow1 * alpha1 + rs1;
        mrow0 = mnew0;
        mrow1 = mnew1;
#pragma unroll
        for (int ni = 0; ni < 8; ni++) {
            Oacc[ni][0] *= alpha0; Oacc[ni][1] *= alpha0;
            Oacc[ni][2] *= alpha1; Oacc[ni][3] *= alpha1;
        }

        // All warps finished reading Ks in the S phase -> Ks reusable as P
        __syncthreads();

        // stash P (tf32) into this warp's private rows of Ks
        const int qr0 = wid * 16 + g;
#pragma unroll
        for (int ni = 0; ni < 8; ni++) {
            const int c = ni * 8 + 2 * tq;
            uint2 s0 = make_uint2(f2tf32(p0[ni][0]), f2tf32(p0[ni][1]));
            uint2 s1 = make_uint2(f2tf32(p1[ni][0]), f2tf32(p1[ni][1]));
            *(uint2*)(Ks + (qr0)     * QP + c) = s0;
            *(uint2*)(Ks + (qr0 + 8) * QP + c) = s1;
        }
        __syncwarp();

        // O += P V : A = Ks-as-P (16 x 64 keys), B = Vs (keys x hd)
#pragma unroll
        for (int ks = 0; ks < 8; ks++) {
            const int kk = ks * 8;
            const int mb = wid * 16;
            uint32_t a0 = Ks[(mb + g)     * QP + kk + tq];
            uint32_t a1 = Ks[(mb + g + 8) * QP + kk + tq];
            uint32_t a2 = Ks[(mb + g)     * QP + kk + tq + 4];
            uint32_t a3 = Ks[(mb + g + 8) * QP + kk + tq + 4];
#pragma unroll
            for (int ni = 0; ni < 8; ni++) {
                const int nb = ni * 8;
                uint32_t b0 = Vs[(kk + tq)     * VP + nb + g];
                uint32_t b1 = Vs[(kk + tq + 4) * VP + nb + g];
                mma_tf32(Oacc[ni], a0, a1, a2, a3, b0, b1);
            }
        }
    }

    // Epilogue
    const float inv0 = 1.0f / lrow0;
    const float inv1 = 1.0f / lrow1;
    float* obase = out + (size_t)b * Sq * Dq + (size_t)h * HDq;
#pragma unroll
    for (int ni = 0; ni < 8; ni++) {
        const int c = ni * 8 + 2 * tq;
        float2 o0 = make_float2(Oacc[ni][0] * inv0, Oacc[ni][1] * inv0);
        float2 o1 = make_float2(Oacc[ni][2] * inv1, Oacc[ni][3] * inv1);
        *(float2*)(obase + (size_t)(q0 + r0) * Dq + c) = o0;
        *(float2*)(obase + (size_t)(q0 + r1) * Dq + c) = o1;
    }
}

// ---------------------------------------------------------------------------
extern "C" void kernel_launch(void* const* d_in, const int* in_sizes, int n_in,
                              void* d_out, int out_size)
{
    const float* x    = (const float*)d_in[0];
    const float* mask = (const float*)d_in[1];
    const float* Wqkv = (const float*)d_in[2];
    const float* bqkv = (const float*)d_in[3];
    const float* Wo   = (const float*)d_in[4];
    const float* bo   = (const float*)d_in[5];
    float* out = (float*)d_out;

    float* qkv  = nullptr;
    float* vals = nullptr;
    cudaGetSymbolAddress((void**)&qkv,  g_qkv);
    cudaGetSymbolAddress((void**)&vals, g_vals);

    const int gemm_smem = 2 * 128 * GP * (int)sizeof(uint32_t);   // 69632 B
    cudaFuncSetAttribute(gemm_tf32_nt_bias<true>,
                         cudaFuncAttributeMaxDynamicSharedMemorySize, gemm_smem);
    cudaFuncSetAttribute(gemm_tf32_nt_bias<false>,
                         cudaFuncAttributeMaxDynamicSharedMemorySize, gemm_smem);

    // 1) QKV projection (epilogue rounds output to tf32 for flash raw copies)
    {
        dim3 grid((3 * Dq) / 128, (Bq * Sq) / 128);
        gemm_tf32_nt_bias<true><<<grid, 256, gemm_smem>>>(Bq * Sq, 3 * Dq, Dq,
                                                          x, Wqkv, bqkv, qkv);
    }

    // 2) Flash attention (verbatim round-11)
    {
        const int smem = (2 * 64 * QP + 64 * VP) * (int)sizeof(uint32_t); // 53248 B
        cudaFuncSetAttribute(flash_attn_tf32,
                             cudaFuncAttributeMaxDynamicSharedMemorySize, smem);
        dim3 grid(Sq / 64, Hq, Bq);
        flash_attn_tf32<<<grid, 128, smem>>>(qkv, mask, vals);
    }

    // 3) Output projection (plain fp32 epilogue)
    {
        dim3 grid(Dq / 128, (Bq * Sq) / 128);
        gemm_tf32_nt_bias<false><<<grid, 256, gemm_smem>>>(Bq * Sq, Dq, Dq,
                                                           vals, Wo, bo, out);
    }
}

// round 15
// speedup vs baseline: 1.0805x; 1.0805x over previous
#include <cuda_runtime.h>
#include <math.h>
#include <stdint.h>

// Problem constants
#define Bq  2
#define Sq  2048
#define Dq  1024
#define Hq  16
#define HDq 64

__device__ float g_qkv[(size_t)Bq * Sq * 3 * Dq];   // (B,S,3D), tf32-rounded
__device__ float g_vals[(size_t)Bq * Sq * Dq];      // (B,S,D)

// ---------------------------------------------------------------------------
// tf32 helpers
// ---------------------------------------------------------------------------
__device__ __forceinline__ uint32_t f2tf32(float x) {
    uint32_t r;
    asm("cvt.rna.tf32.f32 %0, %1;" : "=r"(r) : "f"(x));
    return r;
}
__device__ __forceinline__ float roundtf(float x) {
    return __uint_as_float(f2tf32(x));
}

__device__ __forceinline__ void mma_tf32(float c[4],
                                         uint32_t a0, uint32_t a1, uint32_t a2, uint32_t a3,
                                         uint32_t b0, uint32_t b1) {
    asm volatile(
        "mma.sync.aligned.m16n8k8.row.col.f32.tf32.tf32.f32 "
        "{%0,%1,%2,%3}, {%4,%5,%6,%7}, {%8,%9}, {%0,%1,%2,%3};"
        : "+f"(c[0]), "+f"(c[1]), "+f"(c[2]), "+f"(c[3])
        : "r"(a0), "r"(a1), "r"(a2), "r"(a3), "r"(b0), "r"(b1));
}

// ---------------------------------------------------------------------------
// tf32 GEMM: C[M,N] = A[M,K] @ W[N,K]^T + bias[N]
// FROZEN: verbatim round-2/11 kernel (static smem, BK=32) — measured best
// across 5 loader/shape variants. Optional tf32-rounded epilogue.
// ---------------------------------------------------------------------------
template <bool ROUND>
__global__ void __launch_bounds__(256)
gemm_tf32_nt_bias(int M, int N, int K,
                  const float* __restrict__ A,
                  const float* __restrict__ W,
                  const float* __restrict__ bias,
                  float* __restrict__ C)
{
    constexpr int BK = 32, PITCH = 36;
    __shared__ uint32_t As[128][PITCH];
    __shared__ uint32_t Ws[128][PITCH];

    const int tid  = threadIdx.x;
    const int lane = tid & 31;
    const int w    = tid >> 5;
    const int wr   = w >> 2;      // 0..1
    const int wc   = w & 3;       // 0..3
    const int m0   = blockIdx.y * 128;
    const int n0   = blockIdx.x * 128;

    const int g  = lane >> 2;     // groupID 0..7
    const int tq = lane & 3;      // threadID in quad 0..3

    float acc[4][4][4];
#pragma unroll
    for (int i = 0; i < 4; i++)
#pragma unroll
        for (int j = 0; j < 4; j++)
#pragma unroll
            for (int e = 0; e < 4; e++) acc[i][j][e] = 0.0f;

    const int lrow = tid >> 3;          // 0..31
    const int lc4  = (tid & 7) << 2;    // 0..28

    for (int k0 = 0; k0 < K; k0 += BK) {
#pragma unroll
        for (int rr = 0; rr < 4; rr++) {
            const int r = lrow + rr * 32;
            float4 av = *(const float4*)(A + (size_t)(m0 + r) * K + k0 + lc4);
            As[r][lc4 + 0] = f2tf32(av.x); As[r][lc4 + 1] = f2tf32(av.y);
            As[r][lc4 + 2] = f2tf32(av.z); As[r][lc4 + 3] = f2tf32(av.w);
            float4 wv = *(const float4*)(W + (size_t)(n0 + r) * K + k0 + lc4);
            Ws[r][lc4 + 0] = f2tf32(wv.x); Ws[r][lc4 + 1] = f2tf32(wv.y);
            Ws[r][lc4 + 2] = f2tf32(wv.z); Ws[r][lc4 + 3] = f2tf32(wv.w);
        }
        __syncthreads();

#pragma unroll
        for (int ks = 0; ks < 4; ks++) {
            const int kk = ks * 8;
            uint32_t af[4][4];
#pragma unroll
            for (int mi = 0; mi < 4; mi++) {
                const int rb = wr * 64 + mi * 16;
                af[mi][0] = As[rb + g    ][kk + tq    ];
                af[mi][1] = As[rb + g + 8][kk + tq    ];
                af[mi][2] = As[rb + g    ][kk + tq + 4];
                af[mi][3] = As[rb + g + 8][kk + tq + 4];
            }
            uint32_t bf[4][2];
#pragma unroll
            for (int ni = 0; ni < 4; ni++) {
                const int cb = wc * 32 + ni * 8;
                bf[ni][0] = Ws[cb + g][kk + tq    ];
                bf[ni][1] = Ws[cb + g][kk + tq + 4];
            }
#pragma unroll
            for (int mi = 0; mi < 4; mi++)
#pragma unroll
                for (int ni = 0; ni < 4; ni++)
                    mma_tf32(acc[mi][ni],
                             af[mi][0], af[mi][1], af[mi][2], af[mi][3],
                             bf[ni][0], bf[ni][1]);
        }
        __syncthreads();
    }

#pragma unroll
    for (int mi = 0; mi < 4; mi++) {
        const int r0 = m0 + wr * 64 + mi * 16 + g;
#pragma unroll
        for (int ni = 0; ni < 4; ni++) {
            const int c = n0 + wc * 32 + ni * 8 + 2 * tq;
            const float b0v = bias[c], b1v = bias[c + 1];
            float2 o0, o1;
            if (ROUND) {
                o0 = make_float2(roundtf(acc[mi][ni][0] + b0v), roundtf(acc[mi][ni][1] + b1v));
                o1 = make_float2(roundtf(acc[mi][ni][2] + b0v), roundtf(acc[mi][ni][3] + b1v));
            } else {
                o0 = make_float2(acc[mi][ni][0] + b0v, acc[mi][ni][1] + b1v);
                o1 = make_float2(acc[mi][ni][2] + b0v, acc[mi][ni][3] + b1v);
            }
            *(float2*)(C + (size_t)r0 * N + c)       = o0;
            *(float2*)(C + (size_t)(r0 + 8) * N + c) = o1;
        }
    }
}

// ---------------------------------------------------------------------------
// Flash attention, tf32. Round-15: q-tile 128 rows, 256 threads (8 warps),
// 2 CTAs/SM (smem 105472 B) -> same 16 warps/SM as r11 but HALF the K/V
// gmem/L2 traffic and 2 block barriers per k-tile (dedicated P buffer).
// Per-warp internals identical to the proven round-11 kernel.
// ---------------------------------------------------------------------------
#define QP 68
#define VP 72

__global__ void __launch_bounds__(256, 2)
flash_attn_tf32(const float* __restrict__ qkv,
                const float* __restrict__ mask,
                float* __restrict__ out)
{
    extern __shared__ uint32_t sm[];
    uint32_t* Qs = sm;                         // [128][QP] (persistent)
    uint32_t* Ks = sm + 128 * QP;              // [64][QP]
    uint32_t* Ps = sm + 128 * QP + 64 * QP;    // [128][QP]
    uint32_t* Vs = sm + 2 * 128 * QP + 64 * QP;// [64][VP]

    const int tid  = threadIdx.x;
    const int lane = tid & 31;
    const int wid  = tid >> 5;     // 0..7 -> q rows [wid*16, +16)
    const int g    = lane >> 2;    // 0..7
    const int tq   = lane & 3;     // 0..3

    const int q0 = blockIdx.x * 128;
    const int h  = blockIdx.y;
    const int b  = blockIdx.z;
    const float scale = 0.125f;

    const uint32_t* base =
        (const uint32_t*)(qkv + (size_t)b * Sq * (3 * Dq) + (size_t)h * (3 * HDq));

    // Load Q tile (128 x 64), already tf32-rounded -> raw copy
#pragma unroll
    for (int rr = 0; rr < 8; rr++) {
        const int r  = (tid >> 4) + rr * 16;
        const int c4 = (tid & 15) << 2;
        uint4 v = *(const uint4*)(base + (size_t)(q0 + r) * (3 * Dq) + c4);
        *(uint4*)(Qs + r * QP + c4) = v;
    }

    float Oacc[8][4];
#pragma unroll
    for (int ni = 0; ni < 8; ni++)
#pragma unroll
        for (int e = 0; e < 4; e++) Oacc[ni][e] = 0.0f;
    float mrow0 = -INFINITY, mrow1 = -INFINITY;
    float lrow0 = 0.0f, lrow1 = 0.0f;

    const int r0 = wid * 16 + g;   // this thread's first q row (within tile)
    const int r1 = r0 + 8;
    const int mb = wid * 16;

    for (int kt = 0; kt < Sq / 64; kt++) {
        const int k0t = kt * 64;
        __syncthreads();   // prev PV done reading Ks/Vs; Q visible on 1st iter

        // Load K and V tiles (pre-rounded) -> raw uint4 copies
#pragma unroll
        for (int rr = 0; rr < 4; rr++) {
            const int r  = (tid >> 4) + rr * 16;
            const int c4 = (tid & 15) << 2;
            uint4 kv = *(const uint4*)(base + 64 + (size_t)(k0t + r) * (3 * Dq) + c4);
            *(uint4*)(Ks + r * QP + c4) = kv;
            uint4 vv = *(const uint4*)(base + 128 + (size_t)(k0t + r) * (3 * Dq) + c4);
            *(uint4*)(Vs + r * VP + c4) = vv;
        }
        __syncthreads();

        // S = Q K^T : warp computes 16 x 64 (8 n-tiles)
        float Sacc[8][4];
#pragma unroll
        for (int ni = 0; ni < 8; ni++)
#pragma unroll
            for (int e = 0; e < 4; e++) Sacc[ni][e] = 0.0f;

#pragma unroll
        for (int ks = 0; ks < 8; ks++) {
            const int kk = ks * 8;
            uint32_t a0 = Qs[(mb + g)     * QP + kk + tq];
            uint32_t a1 = Qs[(mb + g + 8) * QP + kk + tq];
            uint32_t a2 = Qs[(mb + g)     * QP + kk + tq + 4];
            uint32_t a3 = Qs[(mb + g + 8) * QP + kk + tq + 4];
#pragma unroll
            for (int ni = 0; ni < 8; ni++) {
                const int nb = ni * 8;
                uint32_t b0 = Ks[(nb + g) * QP + kk + tq];
                uint32_t b1 = Ks[(nb + g) * QP + kk + tq + 4];
                mma_tf32(Sacc[ni], a0, a1, a2, a3, b0, b1);
            }
        }

        // scale + mask + online softmax (rows r0, r1; cols 8*ni + 2*tq {,+1})
        float p0[8][2], p1[8][2];
        float rmax0 = -INFINITY, rmax1 = -INFINITY;
#pragma unroll
        for (int ni = 0; ni < 8; ni++) {
            const int c = ni * 8 + 2 * tq;
            float2 mk0 = *(const float2*)(mask + (size_t)(q0 + r0) * Sq + k0t + c);
            float2 mk1 = *(const float2*)(mask + (size_t)(q0 + r1) * Sq + k0t + c);
            p0[ni][0] = Sacc[ni][0] * scale + mk0.x;
            p0[ni][1] = Sacc[ni][1] * scale + mk0.y;
            p1[ni][0] = Sacc[ni][2] * scale + mk1.x;
            p1[ni][1] = Sacc[ni][3] * scale + mk1.y;
            rmax0 = fmaxf(rmax0, fmaxf(p0[ni][0], p0[ni][1]));
            rmax1 = fmaxf(rmax1, fmaxf(p1[ni][0], p1[ni][1]));
        }
#pragma unroll
        for (int off = 1; off < 4; off <<= 1) {
            rmax0 = fmaxf(rmax0, __shfl_xor_sync(0xffffffffu, rmax0, off));
            rmax1 = fmaxf(rmax1, __shfl_xor_sync(0xffffffffu, rmax1, off));
        }
        const float mnew0 = fmaxf(mrow0, rmax0);
        const float mnew1 = fmaxf(mrow1, rmax1);
        const float alpha0 = __expf(mrow0 - mnew0);
        const float alpha1 = __expf(mrow1 - mnew1);
        float rs0 = 0.0f, rs1 = 0.0f;
#pragma unroll
        for (int ni = 0; ni < 8; ni++) {
            p0[ni][0] = __expf(p0[ni][0] - mnew0);
            p0[ni][1] = __expf(p0[ni][1] - mnew0);
            p1[ni][0] = __expf(p1[ni][0] - mnew1);
            p1[ni][1] = __expf(p1[ni][1] - mnew1);
            rs0 += p0[ni][0] + p0[ni][1];
            rs1 += p1[ni][0] + p1[ni][1];
        }
#pragma unroll
        for (int off = 1; off < 4; off <<= 1) {
            rs0 += __shfl_xor_sync(0xffffffffu, rs0, off);
            rs1 += __shfl_xor_sync(0xffffffffu, rs1, off);
        }
        lrow0 = lrow0 * alpha0 + rs0;
        lrow1 = lrow1 * alpha1 + rs1;
        mrow0 = mnew0;
        mrow1 = mnew1;
#pragma unroll
        for (int ni = 0; ni < 8; ni++) {
            Oacc[ni][0] *= alpha0; Oacc[ni][1] *= alpha0;
            Oacc[ni][2] *= alpha1; Oacc[ni][3] *= alpha1;
        }

        // stash P (tf32) into this warp's private rows of Ps (warp-local)
        const int qr0 = wid * 16 + g;
#pragma unroll
        for (int ni = 0; ni < 8; ni++) {
            const int c = ni * 8 + 2 * tq;
            uint2 s0 = make_uint2(f2tf32(p0[ni][0]), f2tf32(p0[ni][1]));
            uint2 s1 = make_uint2(f2tf32(p1[ni][0]), f2tf32(p1[ni][1]));
            *(uint2*)(Ps + (qr0)     * QP + c) = s0;
            *(uint2*)(Ps + (qr0 + 8) * QP + c) = s1;
        }
        __syncwarp();

        // O += P V : A = Ps (16 x 64 keys), B = Vs (keys x hd)
#pragma unroll
        for (int ks = 0; ks < 8; ks++) {
            const int kk = ks * 8;
            uint32_t a0 = Ps[(mb + g)     * QP + kk + tq];
            uint32_t a1 = Ps[(mb + g + 8) * QP + kk + tq];
            uint32_t a2 = Ps[(mb + g)     * QP + kk + tq + 4];
            uint32_t a3 = Ps[(mb + g + 8) * QP + kk + tq + 4];
#pragma unroll
            for (int ni = 0; ni < 8; ni++) {
                const int nb = ni * 8;
                uint32_t b0 = Vs[(kk + tq)     * VP + nb + g];
                uint32_t b1 = Vs[(kk + tq + 4) * VP + nb + g];
                mma_tf32(Oacc[ni], a0, a1, a2, a3, b0, b1);
            }
        }
    }

    // Epilogue
    const float inv0 = 1.0f / lrow0;
    const float inv1 = 1.0f / lrow1;
    float* obase = out + (size_t)b * Sq * Dq + (size_t)h * HDq;
#pragma unroll
    for (int ni = 0; ni < 8; ni++) {
        const int c = ni * 8 + 2 * tq;
        float2 o0 = make_float2(Oacc[ni][0] * inv0, Oacc[ni][1] * inv0);
        float2 o1 = make_float2(Oacc[ni][2] * inv1, Oacc[ni][3] * inv1);
        *(float2*)(obase + (size_t)(q0 + r0) * Dq + c) = o0;
        *(float2*)(obase + (size_t)(q0 + r1) * Dq + c) = o1;
    }
}

// ---------------------------------------------------------------------------
extern "C" void kernel_launch(void* const* d_in, const int* in_sizes, int n_in,
                              void* d_out, int out_size)
{
    const float* x    = (const float*)d_in[0];
    const float* mask = (const float*)d_in[1];
    const float* Wqkv = (const float*)d_in[2];
    const float* bqkv = (const float*)d_in[3];
    const float* Wo   = (const float*)d_in[4];
    const float* bo   = (const float*)d_in[5];
    float* out = (float*)d_out;

    float* qkv  = nullptr;
    float* vals = nullptr;
    cudaGetSymbolAddress((void**)&qkv,  g_qkv);
    cudaGetSymbolAddress((void**)&vals, g_vals);

    // 1) QKV projection (epilogue rounds output to tf32 for flash raw copies)
    {
        dim3 grid((3 * Dq) / 128, (Bq * Sq) / 128);
        gemm_tf32_nt_bias<true><<<grid, 256>>>(Bq * Sq, 3 * Dq, Dq, x, Wqkv, bqkv, qkv);
    }

    // 2) Flash attention (128-row q tiles, 8 warps, 2 CTAs/SM)
    {
        const int smem = (2 * 128 * QP + 64 * QP + 64 * VP) * (int)sizeof(uint32_t); // 105472
        cudaFuncSetAttribute(flash_attn_tf32,
                             cudaFuncAttributeMaxDynamicSharedMemorySize, smem);
        dim3 grid(Sq / 128, Hq, Bq);
        flash_attn_tf32<<<grid, 256, smem>>>(qkv, mask, vals);
    }

    // 3) Output projection (plain fp32 epilogue)
    {
        dim3 grid(Dq / 128, (Bq * Sq) / 128);
        gemm_tf32_nt_bias<false><<<grid, 256>>>(Bq * Sq, Dq, Dq, vals, Wo, bo, out);
    }
}

// round 16
// speedup vs baseline: 1.1406x; 1.0556x over previous
#include <cuda_runtime.h>
#include <math.h>
#include <stdint.h>

// Problem constants
#define Bq  2
#define Sq  2048
#define Dq  1024
#define Hq  16
#define HDq 64

__device__ float g_qkv[(size_t)Bq * Sq * 3 * Dq];   // (B,S,3D), tf32-rounded
__device__ float g_vals[(size_t)Bq * Sq * Dq];      // (B,S,D)

// ---------------------------------------------------------------------------
// tf32 helpers
// ---------------------------------------------------------------------------
__device__ __forceinline__ uint32_t f2tf32(float x) {
    uint32_t r;
    asm("cvt.rna.tf32.f32 %0, %1;" : "=r"(r) : "f"(x));
    return r;
}
__device__ __forceinline__ float roundtf(float x) {
    return __uint_as_float(f2tf32(x));
}

__device__ __forceinline__ void mma_tf32(float c[4],
                                         uint32_t a0, uint32_t a1, uint32_t a2, uint32_t a3,
                                         uint32_t b0, uint32_t b1) {
    asm volatile(
        "mma.sync.aligned.m16n8k8.row.col.f32.tf32.tf32.f32 "
        "{%0,%1,%2,%3}, {%4,%5,%6,%7}, {%8,%9}, {%0,%1,%2,%3};"
        : "+f"(c[0]), "+f"(c[1]), "+f"(c[2]), "+f"(c[3])
        : "r"(a0), "r"(a1), "r"(a2), "r"(a3), "r"(b0), "r"(b1));
}

// ---------------------------------------------------------------------------
// tf32 GEMM: C[M,N] = A[M,K] @ W[N,K]^T + bias[N]
// FROZEN: verbatim round-2/11 kernel (static smem, BK=32) — measured best
// across 6 loader/shape variants. Optional tf32-rounded epilogue.
// ---------------------------------------------------------------------------
template <bool ROUND>
__global__ void __launch_bounds__(256)
gemm_tf32_nt_bias(int M, int N, int K,
                  const float* __restrict__ A,
                  const float* __restrict__ W,
                  const float* __restrict__ bias,
                  float* __restrict__ C)
{
    constexpr int BK = 32, PITCH = 36;
    __shared__ uint32_t As[128][PITCH];
    __shared__ uint32_t Ws[128][PITCH];

    const int tid  = threadIdx.x;
    const int lane = tid & 31;
    const int w    = tid >> 5;
    const int wr   = w >> 2;      // 0..1
    const int wc   = w & 3;       // 0..3
    const int m0   = blockIdx.y * 128;
    const int n0   = blockIdx.x * 128;

    const int g  = lane >> 2;     // groupID 0..7
    const int tq = lane & 3;      // threadID in quad 0..3

    float acc[4][4][4];
#pragma unroll
    for (int i = 0; i < 4; i++)
#pragma unroll
        for (int j = 0; j < 4; j++)
#pragma unroll
            for (int e = 0; e < 4; e++) acc[i][j][e] = 0.0f;

    const int lrow = tid >> 3;          // 0..31
    const int lc4  = (tid & 7) << 2;    // 0..28

    for (int k0 = 0; k0 < K; k0 += BK) {
#pragma unroll
        for (int rr = 0; rr < 4; rr++) {
            const int r = lrow + rr * 32;
            float4 av = *(const float4*)(A + (size_t)(m0 + r) * K + k0 + lc4);
            As[r][lc4 + 0] = f2tf32(av.x); As[r][lc4 + 1] = f2tf32(av.y);
            As[r][lc4 + 2] = f2tf32(av.z); As[r][lc4 + 3] = f2tf32(av.w);
            float4 wv = *(const float4*)(W + (size_t)(n0 + r) * K + k0 + lc4);
            Ws[r][lc4 + 0] = f2tf32(wv.x); Ws[r][lc4 + 1] = f2tf32(wv.y);
            Ws[r][lc4 + 2] = f2tf32(wv.z); Ws[r][lc4 + 3] = f2tf32(wv.w);
        }
        __syncthreads();

#pragma unroll
        for (int ks = 0; ks < 4; ks++) {
            const int kk = ks * 8;
            uint32_t af[4][4];
#pragma unroll
            for (int mi = 0; mi < 4; mi++) {
                const int rb = wr * 64 + mi * 16;
                af[mi][0] = As[rb + g    ][kk + tq    ];
                af[mi][1] = As[rb + g + 8][kk + tq    ];
                af[mi][2] = As[rb + g    ][kk + tq + 4];
                af[mi][3] = As[rb + g + 8][kk + tq + 4];
            }
            uint32_t bf[4][2];
#pragma unroll
            for (int ni = 0; ni < 4; ni++) {
                const int cb = wc * 32 + ni * 8;
                bf[ni][0] = Ws[cb + g][kk + tq    ];
                bf[ni][1] = Ws[cb + g][kk + tq + 4];
            }
#pragma unroll
            for (int mi = 0; mi < 4; mi++)
#pragma unroll
                for (int ni = 0; ni < 4; ni++)
                    mma_tf32(acc[mi][ni],
                             af[mi][0], af[mi][1], af[mi][2], af[mi][3],
                             bf[ni][0], bf[ni][1]);
        }
        __syncthreads();
    }

#pragma unroll
    for (int mi = 0; mi < 4; mi++) {
        const int r0 = m0 + wr * 64 + mi * 16 + g;
#pragma unroll
        for (int ni = 0; ni < 4; ni++) {
            const int c = n0 + wc * 32 + ni * 8 + 2 * tq;
            const float b0v = bias[c], b1v = bias[c + 1];
            float2 o0, o1;
            if (ROUND) {
                o0 = make_float2(roundtf(acc[mi][ni][0] + b0v), roundtf(acc[mi][ni][1] + b1v));
                o1 = make_float2(roundtf(acc[mi][ni][2] + b0v), roundtf(acc[mi][ni][3] + b1v));
            } else {
                o0 = make_float2(acc[mi][ni][0] + b0v, acc[mi][ni][1] + b1v);
                o1 = make_float2(acc[mi][ni][2] + b0v, acc[mi][ni][3] + b1v);
            }
            *(float2*)(C + (size_t)r0 * N + c)       = o0;
            *(float2*)(C + (size_t)(r0 + 8) * N + c) = o1;
        }
    }
}

// ---------------------------------------------------------------------------
// Flash attention, tf32. Verbatim round-11 kernel (measured best: 637.4us
// total) + ONE zero-register change: prefetch.global.L1 of this thread's
// mask lines at the top of each k-tile iteration, so the mask LDGs issued
// after the S-MMA hit L1 (~32cyc) instead of L2 (~250cyc).
// Grid (S/64, H, B), 128 threads, 4 CTAs/SM, smem 53248 B.
// ---------------------------------------------------------------------------
#define QP 68
#define VP 72

__global__ void __launch_bounds__(128, 4)
flash_attn_tf32(const float* __restrict__ qkv,
                const float* __restrict__ mask,
                float* __restrict__ out)
{
    extern __shared__ uint32_t sm[];
    uint32_t* Qs = sm;                  // [64][QP]  (persistent)
    uint32_t* Ks = sm + 64 * QP;        // [64][QP]  (doubles as P after S-phase)
    uint32_t* Vs = sm + 2 * 64 * QP;    // [64][VP]

    const int tid  = threadIdx.x;
    const int lane = tid & 31;
    const int wid  = tid >> 5;     // 0..3 -> q rows [wid*16, +16)
    const int g    = lane >> 2;    // 0..7
    const int tq   = lane & 3;     // 0..3

    const int q0 = blockIdx.x * 64;
    const int h  = blockIdx.y;
    const int b  = blockIdx.z;
    const float scale = 0.125f;

    const uint32_t* base =
        (const uint32_t*)(qkv + (size_t)b * Sq * (3 * Dq) + (size_t)h * (3 * HDq));

    // Load Q tile (64 x 64), already tf32-rounded -> raw copy
#pragma unroll
    for (int rr = 0; rr < 8; rr++) {
        const int r  = (tid >> 4) + rr * 8;
        const int c4 = (tid & 15) << 2;
        uint4 v = *(const uint4*)(base + (size_t)(q0 + r) * (3 * Dq) + c4);
        *(uint4*)(Qs + r * QP + c4) = v;
    }

    float Oacc[8][4];
#pragma unroll
    for (int ni = 0; ni < 8; ni++)
#pragma unroll
        for (int e = 0; e < 4; e++) Oacc[ni][e] = 0.0f;
    float mrow0 = -INFINITY, mrow1 = -INFINITY;
    float lrow0 = 0.0f, lrow1 = 0.0f;

    const int r0 = wid * 16 + g;   // this thread's first q row (within tile)
    const int r1 = r0 + 8;

    // mask prefetch address: quad lanes cover the 4 cache lines the quad's
    // two rows touch per tile. tq bit1 selects row, bit0 selects 128B line.
    const float* mpf_row =
        mask + (size_t)(q0 + ((tq & 2) ? r1 : r0)) * Sq + (tq & 1) * 32;

    for (int kt = 0; kt < Sq / 64; kt++) {
        const int k0t = kt * 64;

        // fire-and-forget L1 prefetch of this tile's mask lines (consumed
        // ~1500+ cycles later, after the K/V load + S-MMA phases)
        asm volatile("prefetch.global.L1 [%0];" :: "l"(mpf_row + k0t));

        __syncthreads();   // prev PV done reading Ks(P)/Vs; Q visible on 1st iter

        // Load K and V tiles (pre-rounded) -> raw uint4 copies
#pragma unroll
        for (int rr = 0; rr < 8; rr++) {
            const int r  = (tid >> 4) + rr * 8;
            const int c4 = (tid & 15) << 2;
            uint4 kv = *(const uint4*)(base + 64 + (size_t)(k0t + r) * (3 * Dq) + c4);
            *(uint4*)(Ks + r * QP + c4) = kv;
            uint4 vv = *(const uint4*)(base + 128 + (size_t)(k0t + r) * (3 * Dq) + c4);
            *(uint4*)(Vs + r * VP + c4) = vv;
        }
        __syncthreads();

        // S = Q K^T : warp computes 16 x 64 (8 n-tiles)
        float Sacc[8][4];
#pragma unroll
        for (int ni = 0; ni < 8; ni++)
#pragma unroll
            for (int e = 0; e < 4; e++) Sacc[ni][e] = 0.0f;

#pragma unroll
        for (int ks = 0; ks < 8; ks++) {
            const int kk = ks * 8;
            const int mb = wid * 16;
            uint32_t a0 = Qs[(mb + g)     * QP + kk + tq];
            uint32_t a1 = Qs[(mb + g + 8) * QP + kk + tq];
            uint32_t a2 = Qs[(mb + g)     * QP + kk + tq + 4];
            uint32_t a3 = Qs[(mb + g + 8) * QP + kk + tq + 4];
#pragma unroll
            for (int ni = 0; ni < 8; ni++) {
                const int nb = ni * 8;
                uint32_t b0 = Ks[(nb + g) * QP + kk + tq];
                uint32_t b1 = Ks[(nb + g) * QP + kk + tq + 4];
                mma_tf32(Sacc[ni], a0, a1, a2, a3, b0, b1);
            }
        }

        // scale + mask + online softmax (rows r0, r1; cols 8*ni + 2*tq {,+1})
        float p0[8][2], p1[8][2];
        float rmax0 = -INFINITY, rmax1 = -INFINITY;
#pragma unroll
        for (int ni = 0; ni < 8; ni++) {
            const int c = ni * 8 + 2 * tq;
            float2 mk0 = *(const float2*)(mask + (size_t)(q0 + r0) * Sq + k0t + c);
            float2 mk1 = *(const float2*)(mask + (size_t)(q0 + r1) * Sq + k0t + c);
            p0[ni][0] = Sacc[ni][0] * scale + mk0.x;
            p0[ni][1] = Sacc[ni][1] * scale + mk0.y;
            p1[ni][0] = Sacc[ni][2] * scale + mk1.x;
            p1[ni][1] = Sacc[ni][3] * scale + mk1.y;
            rmax0 = fmaxf(rmax0, fmaxf(p0[ni][0], p0[ni][1]));
            rmax1 = fmaxf(rmax1, fmaxf(p1[ni][0], p1[ni][1]));
        }
#pragma unroll
        for (int off = 1; off < 4; off <<= 1) {
            rmax0 = fmaxf(rmax0, __shfl_xor_sync(0xffffffffu, rmax0, off));
            rmax1 = fmaxf(rmax1, __shfl_xor_sync(0xffffffffu, rmax1, off));
        }
        const float mnew0 = fmaxf(mrow0, rmax0);
        const float mnew1 = fmaxf(mrow1, rmax1);
        const float alpha0 = __expf(mrow0 - mnew0);
        const float alpha1 = __expf(mrow1 - mnew1);
        float rs0 = 0.0f, rs1 = 0.0f;
#pragma unroll
        for (int ni = 0; ni < 8; ni++) {
            p0[ni][0] = __expf(p0[ni][0] - mnew0);
            p0[ni][1] = __expf(p0[ni][1] - mnew0);
            p1[ni][0] = __expf(p1[ni][0] - mnew1);
            p1[ni][1] = __expf(p1[ni][1] - mnew1);
            rs0 += p0[ni][0] + p0[ni][1];
            rs1 += p1[ni][0] + p1[ni][1];
        }
#pragma unroll
        for (int off = 1; off < 4; off <<= 1) {
            rs0 += __shfl_xor_sync(0xffffffffu, rs0, off);
            rs1 += __shfl_xor_sync(0xffffffffu, rs1, off);
        }
        lrow0 = lrow0 * alpha0 + rs0;
        lrow1 = lrow1 * alpha1 + rs1;
        mrow0 = mnew0;
        mrow1 = mnew1;
#pragma unroll
        for (int ni = 0; ni < 8; ni++) {
            Oacc[ni][0] *= alpha0; Oacc[ni][1] *= alpha0;
            Oacc[ni][2] *= alpha1; Oacc[ni][3] *= alpha1;
        }

        // All warps finished reading Ks in the S phase -> Ks reusable as P
        __syncthreads();

        // stash P (tf32) into this warp's private rows of Ks
        const int qr0 = wid * 16 + g;
#pragma unroll
        for (int ni = 0; ni < 8; ni++) {
            const int c = ni * 8 + 2 * tq;
            uint2 s0 = make_uint2(f2tf32(p0[ni][0]), f2tf32(p0[ni][1]));
            uint2 s1 = make_uint2(f2tf32(p1[ni][0]), f2tf32(p1[ni][1]));
            *(uint2*)(Ks + (qr0)     * QP + c) = s0;
            *(uint2*)(Ks + (qr0 + 8) * QP + c) = s1;
        }
        __syncwarp();

        // O += P V : A = Ks-as-P (16 x 64 keys), B = Vs (keys x hd)
#pragma unroll
        for (int ks = 0; ks < 8; ks++) {
            const int kk = ks * 8;
            const int mb = wid * 16;
            uint32_t a0 = Ks[(mb + g)     * QP + kk + tq];
            uint32_t a1 = Ks[(mb + g + 8) * QP + kk + tq];
            uint32_t a2 = Ks[(mb + g)     * QP + kk + tq + 4];
            uint32_t a3 = Ks[(mb + g + 8) * QP + kk + tq + 4];
#pragma unroll
            for (int ni = 0; ni < 8; ni++) {
                const int nb = ni * 8;
                uint32_t b0 = Vs[(kk + tq)     * VP + nb + g];
                uint32_t b1 = Vs[(kk + tq + 4) * VP + nb + g];
                mma_tf32(Oacc[ni], a0, a1, a2, a3, b0, b1);
            }
        }
    }

    // Epilogue
    const float inv0 = 1.0f / lrow0;
    const float inv1 = 1.0f / lrow1;
    float* obase = out + (size_t)b * Sq * Dq + (size_t)h * HDq;
#pragma unroll
    for (int ni = 0; ni < 8; ni++) {
        const int c = ni * 8 + 2 * tq;
        float2 o0 = make_float2(Oacc[ni][0] * inv0, Oacc[ni][1] * inv0);
        float2 o1 = make_float2(Oacc[ni][2] * inv1, Oacc[ni][3] * inv1);
        *(float2*)(obase + (size_t)(q0 + r0) * Dq + c) = o0;
        *(float2*)(obase + (size_t)(q0 + r1) * Dq + c) = o1;
    }
}

// ---------------------------------------------------------------------------
extern "C" void kernel_launch(void* const* d_in, const int* in_sizes, int n_in,
                              void* d_out, int out_size)
{
    const float* x    = (const float*)d_in[0];
    const float* mask = (const float*)d_in[1];
    const float* Wqkv = (const float*)d_in[2];
    const float* bqkv = (const float*)d_in[3];
    const float* Wo   = (const float*)d_in[4];
    const float* bo   = (const float*)d_in[5];
    float* out = (float*)d_out;

    float* qkv  = nullptr;
    float* vals = nullptr;
    cudaGetSymbolAddress((void**)&qkv,  g_qkv);
    cudaGetSymbolAddress((void**)&vals, g_vals);

    // 1) QKV projection (epilogue rounds output to tf32 for flash raw copies)
    {
        dim3 grid((3 * Dq) / 128, (Bq * Sq) / 128);
        gemm_tf32_nt_bias<true><<<grid, 256>>>(Bq * Sq, 3 * Dq, Dq, x, Wqkv, bqkv, qkv);
    }

    // 2) Flash attention (r11 + mask L1 prefetch, 4 CTAs/SM)
    {
        const int smem = (2 * 64 * QP + 64 * VP) * (int)sizeof(uint32_t); // 53248 B
        cudaFuncSetAttribute(flash_attn_tf32,
                             cudaFuncAttributeMaxDynamicSharedMemorySize, smem);
        dim3 grid(Sq / 64, Hq, Bq);
        flash_attn_tf32<<<grid, 128, smem>>>(qkv, mask, vals);
    }

    // 3) Output projection (plain fp32 epilogue)
    {
        dim3 grid(Dq / 128, (Bq * Sq) / 128);
        gemm_tf32_nt_bias<false><<<grid, 256>>>(Bq * Sq, Dq, Dq, vals, Wo, bo, out);
    }
}

// round 17
// speedup vs baseline: 1.2511x; 1.0968x over previous
#include <cuda_runtime.h>
#include <cuda_fp16.h>
#include <math.h>
#include <stdint.h>

// Problem constants
#define Bq  2
#define Sq  2048
#define Dq  1024
#define Hq  16
#define HDq 64

__device__ float  g_qkv[(size_t)Bq * Sq * 3 * Dq];       // V cols tf32-rounded (q/k cols unused)
__device__ __half g_qkh[(size_t)Bq * Sq * Hq * 128];     // per (b,s,h): 64 q + 64 k halves
__device__ float  g_vals[(size_t)Bq * Sq * Dq];          // (B,S,D)

// ---------------------------------------------------------------------------
// helpers
// ---------------------------------------------------------------------------
__device__ __forceinline__ uint32_t f2tf32(float x) {
    uint32_t r;
    asm("cvt.rna.tf32.f32 %0, %1;" : "=r"(r) : "f"(x));
    return r;
}
__device__ __forceinline__ float roundtf(float x) {
    return __uint_as_float(f2tf32(x));
}

__device__ __forceinline__ void mma_tf32(float c[4],
                                         uint32_t a0, uint32_t a1, uint32_t a2, uint32_t a3,
                                         uint32_t b0, uint32_t b1) {
    asm volatile(
        "mma.sync.aligned.m16n8k8.row.col.f32.tf32.tf32.f32 "
        "{%0,%1,%2,%3}, {%4,%5,%6,%7}, {%8,%9}, {%0,%1,%2,%3};"
        : "+f"(c[0]), "+f"(c[1]), "+f"(c[2]), "+f"(c[3])
        : "r"(a0), "r"(a1), "r"(a2), "r"(a3), "r"(b0), "r"(b1));
}

__device__ __forceinline__ void mma_f16(float c[4],
                                        uint32_t a0, uint32_t a1, uint32_t a2, uint32_t a3,
                                        uint32_t b0, uint32_t b1) {
    asm volatile(
        "mma.sync.aligned.m16n8k16.row.col.f32.f16.f16.f32 "
        "{%0,%1,%2,%3}, {%4,%5,%6,%7}, {%8,%9}, {%0,%1,%2,%3};"
        : "+f"(c[0]), "+f"(c[1]), "+f"(c[2]), "+f"(c[3])
        : "r"(a0), "r"(a1), "r"(a2), "r"(a3), "r"(b0), "r"(b1));
}

// ---------------------------------------------------------------------------
// tf32 GEMM: C[M,N] = A[M,K] @ W[N,K]^T + bias[N]
// FROZEN core (round-2/11). MODE 0: plain fp32 epilogue (out-proj).
// MODE 1 (QKV): per 8-col group, role=(c%192)>>6; q/k roles -> fp16 into
// qkh[b][s][h][128]; v role -> tf32-rounded float into C (g_qkv).
// ---------------------------------------------------------------------------
template <int MODE>
__global__ void __launch_bounds__(256)
gemm_tf32_nt_bias(int M, int N, int K,
                  const float* __restrict__ A,
                  const float* __restrict__ W,
                  const float* __restrict__ bias,
                  float* __restrict__ C,
                  __half* __restrict__ qkh)
{
    constexpr int BK = 32, PITCH = 36;
    __shared__ uint32_t As[128][PITCH];
    __shared__ uint32_t Ws[128][PITCH];

    const int tid  = threadIdx.x;
    const int lane = tid & 31;
    const int w    = tid >> 5;
    const int wr   = w >> 2;      // 0..1
    const int wc   = w & 3;       // 0..3
    const int m0   = blockIdx.y * 128;
    const int n0   = blockIdx.x * 128;

    const int g  = lane >> 2;     // groupID 0..7
    const int tq = lane & 3;      // threadID in quad 0..3

    float acc[4][4][4];
#pragma unroll
    for (int i = 0; i < 4; i++)
#pragma unroll
        for (int j = 0; j < 4; j++)
#pragma unroll
            for (int e = 0; e < 4; e++) acc[i][j][e] = 0.0f;

    const int lrow = tid >> 3;          // 0..31
    const int lc4  = (tid & 7) << 2;    // 0..28

    for (int k0 = 0; k0 < K; k0 += BK) {
#pragma unroll
        for (int rr = 0; rr < 4; rr++) {
            const int r = lrow + rr * 32;
            float4 av = *(const float4*)(A + (size_t)(m0 + r) * K + k0 + lc4);
            As[r][lc4 + 0] = f2tf32(av.x); As[r][lc4 + 1] = f2tf32(av.y);
            As[r][lc4 + 2] = f2tf32(av.z); As[r][lc4 + 3] = f2tf32(av.w);
            float4 wv = *(const float4*)(W + (size_t)(n0 + r) * K + k0 + lc4);
            Ws[r][lc4 + 0] = f2tf32(wv.x); Ws[r][lc4 + 1] = f2tf32(wv.y);
            Ws[r][lc4 + 2] = f2tf32(wv.z); Ws[r][lc4 + 3] = f2tf32(wv.w);
        }
        __syncthreads();

#pragma unroll
        for (int ks = 0; ks < 4; ks++) {
            const int kk = ks * 8;
            uint32_t af[4][4];
#pragma unroll
            for (int mi = 0; mi < 4; mi++) {
                const int rb = wr * 64 + mi * 16;
                af[mi][0] = As[rb + g    ][kk + tq    ];
                af[mi][1] = As[rb + g + 8][kk + tq    ];
                af[mi][2] = As[rb + g    ][kk + tq + 4];
                af[mi][3] = As[rb + g + 8][kk + tq + 4];
            }
            uint32_t bf[4][2];
#pragma unroll
            for (int ni = 0; ni < 4; ni++) {
                const int cb = wc * 32 + ni * 8;
                bf[ni][0] = Ws[cb + g][kk + tq    ];
                bf[ni][1] = Ws[cb + g][kk + tq + 4];
            }
#pragma unroll
            for (int mi = 0; mi < 4; mi++)
#pragma unroll
                for (int ni = 0; ni < 4; ni++)
                    mma_tf32(acc[mi][ni],
                             af[mi][0], af[mi][1], af[mi][2], af[mi][3],
                             bf[ni][0], bf[ni][1]);
        }
        __syncthreads();
    }

#pragma unroll
    for (int mi = 0; mi < 4; mi++) {
        const int r0 = m0 + wr * 64 + mi * 16 + g;   // r0 == b*Sq + s
#pragma unroll
        for (int ni = 0; ni < 4; ni++) {
            const int c = n0 + wc * 32 + ni * 8 + 2 * tq;
            const float b0v = bias[c], b1v = bias[c + 1];
            if (MODE == 1 && ((c % 192) >> 6) < 2) {
                // q/k feature: fp16 into qkh[b][s][h][128]
                const size_t idx =
                    (size_t)r0 * (Hq * 128) + (size_t)(c / 192) * 128 + (c % 192);
                __half2 h0 = __floats2half2_rn(acc[mi][ni][0] + b0v, acc[mi][ni][1] + b1v);
                __half2 h1 = __floats2half2_rn(acc[mi][ni][2] + b0v, acc[mi][ni][3] + b1v);
                *(__half2*)(qkh + idx)                          = h0;
                *(__half2*)(qkh + idx + (size_t)8 * (Hq * 128)) = h1;
            } else {
                float2 o0, o1;
                if (MODE == 1) {   // v feature: tf32-rounded (flash raw-copies V)
                    o0 = make_float2(roundtf(acc[mi][ni][0] + b0v), roundtf(acc[mi][ni][1] + b1v));
                    o1 = make_float2(roundtf(acc[mi][ni][2] + b0v), roundtf(acc[mi][ni][3] + b1v));
                } else {
                    o0 = make_float2(acc[mi][ni][0] + b0v, acc[mi][ni][1] + b1v);
                    o1 = make_float2(acc[mi][ni][2] + b0v, acc[mi][ni][3] + b1v);
                }
                *(float2*)(C + (size_t)r0 * N + c)       = o0;
                *(float2*)(C + (size_t)(r0 + 8) * N + c) = o1;
            }
        }
    }
}

// ---------------------------------------------------------------------------
// Flash attention. S = QK^T via fp16 mma (m16n8k16, half the MMAs/LDS of the
// tf32 path; fp16 mantissa == tf32 mantissa so numerics are equivalent).
// PV stays the proven tf32 path. Dedicated P buffer -> 2 block barriers/tile.
// Grid (S/64, H, B), 128 threads, 4 CTAs/SM, smem 54272 B.
// ---------------------------------------------------------------------------
#define QHP 72   // half pitch for Qh/Kh (36 words: bank = 4g+tq, conflict-free)
#define PFP 68   // float pitch for P
#define VFP 72   // float pitch for V

#define KH_OFF  9216                          // 64*72*2
#define PF_OFF  18432                         // 2*9216
#define VS_OFF  35840                         // 18432 + 64*68*4
#define FL_SMEM 54272                         // 35840 + 64*72*4

__global__ void __launch_bounds__(128, 4)
flash_attn_f16s(const __half* __restrict__ qkh,
                const float* __restrict__ qkv,
                const float* __restrict__ mask,
                float* __restrict__ out)
{
    extern __shared__ char smraw[];
    __half*   Qh = (__half*)smraw;                    // [64][QHP]
    __half*   Kh = (__half*)(smraw + KH_OFF);         // [64][QHP]
    uint32_t* Pf = (uint32_t*)(smraw + PF_OFF);       // [64][PFP]
    uint32_t* Vs = (uint32_t*)(smraw + VS_OFF);       // [64][VFP]
    const uint32_t* Qw = (const uint32_t*)Qh;         // word view (pitch 36)
    const uint32_t* Kw = (const uint32_t*)Kh;

    const int tid  = threadIdx.x;
    const int lane = tid & 31;
    const int wid  = tid >> 5;     // 0..3 -> q rows [wid*16, +16)
    const int g    = lane >> 2;    // 0..7
    const int tq   = lane & 3;     // 0..3

    const int q0 = blockIdx.x * 64;
    const int h  = blockIdx.y;
    const int b  = blockIdx.z;
    const float scale = 0.125f;

    const __half* qk_base =
        qkh + ((size_t)(b * Sq) * Hq + h) * 128;                 // + s*Hq*128
    const uint32_t* vbase =
        (const uint32_t*)(qkv + (size_t)b * Sq * (3 * Dq) + (size_t)h * (3 * HDq) + 128);

    // ---- load Q tile (64 x 64 halves) : raw uint4 copies ----
    {
        const int r  = tid >> 3;            // 0..15
        const int c8 = (tid & 7) * 8;       // 0..56
#pragma unroll
        for (int rr = 0; rr < 4; rr++) {
            const int row = r + rr * 16;
            uint4 v = *(const uint4*)(qk_base + (size_t)(q0 + row) * (Hq * 128) + c8);
            *(uint4*)(Qh + row * QHP + c8) = v;
        }
    }

    float Oacc[8][4];
#pragma unroll
    for (int ni = 0; ni < 8; ni++)
#pragma unroll
        for (int e = 0; e < 4; e++) Oacc[ni][e] = 0.0f;
    float mrow0 = -INFINITY, mrow1 = -INFINITY;
    float lrow0 = 0.0f, lrow1 = 0.0f;

    const int r0 = wid * 16 + g;
    const int r1 = r0 + 8;
    const int mb = wid * 16;

    for (int kt = 0; kt < Sq / 64; kt++) {
        const int k0t = kt * 64;
        __syncthreads();   // prev S done with Kh, prev PV done with Vs; Q ready on 1st

        // ---- load K tile (halves) + V tile (floats) ----
        {
            const int r  = tid >> 3;
            const int c8 = (tid & 7) * 8;
#pragma unroll
            for (int rr = 0; rr < 4; rr++) {
                const int row = r + rr * 16;
                uint4 v = *(const uint4*)(qk_base + 64 +
                                          (size_t)(k0t + row) * (Hq * 128) + c8);
                *(uint4*)(Kh + row * QHP + c8) = v;
            }
            const int vr  = tid >> 4;
            const int vc4 = (tid & 15) << 2;
#pragma unroll
            for (int rr = 0; rr < 8; rr++) {
                const int row = vr + rr * 8;
                uint4 vv = *(const uint4*)(vbase + (size_t)(k0t + row) * (3 * Dq) + vc4);
                *(uint4*)(Vs + row * VFP + vc4) = vv;
            }
        }
        __syncthreads();

        // ---- S = Q K^T : fp16 mma, 4 k16-steps x 8 n-tiles ----
        float Sacc[8][4];
#pragma unroll
        for (int ni = 0; ni < 8; ni++)
#pragma unroll
            for (int e = 0; e < 4; e++) Sacc[ni][e] = 0.0f;

#pragma unroll
        for (int ks = 0; ks < 4; ks++) {
            const int kk = ks * 8;   // word offset (16 halves)
            uint32_t a0 = Qw[(mb + g)     * 36 + kk + tq];
            uint32_t a1 = Qw[(mb + g + 8) * 36 + kk + tq];
            uint32_t a2 = Qw[(mb + g)     * 36 + kk + tq + 4];
            uint32_t a3 = Qw[(mb + g + 8) * 36 + kk + tq + 4];
#pragma unroll
            for (int ni = 0; ni < 8; ni++) {
                const int nb = ni * 8;
                uint32_t b0 = Kw[(nb + g) * 36 + kk + tq];
                uint32_t b1 = Kw[(nb + g) * 36 + kk + tq + 4];
                mma_f16(Sacc[ni], a0, a1, a2, a3, b0, b1);
            }
        }

        // ---- scale + mask + online softmax (identical to round 11) ----
        float p0[8][2], p1[8][2];
        float rmax0 = -INFINITY, rmax1 = -INFINITY;
#pragma unroll
        for (int ni = 0; ni < 8; ni++) {
            const int c = ni * 8 + 2 * tq;
            float2 mk0 = *(const float2*)(mask + (size_t)(q0 + r0) * Sq + k0t + c);
            float2 mk1 = *(const float2*)(mask + (size_t)(q0 + r1) * Sq + k0t + c);
            p0[ni][0] = Sacc[ni][0] * scale + mk0.x;
            p0[ni][1] = Sacc[ni][1] * scale + mk0.y;
            p1[ni][0] = Sacc[ni][2] * scale + mk1.x;
            p1[ni][1] = Sacc[ni][3] * scale + mk1.y;
            rmax0 = fmaxf(rmax0, fmaxf(p0[ni][0], p0[ni][1]));
            rmax1 = fmaxf(rmax1, fmaxf(p1[ni][0], p1[ni][1]));
        }
#pragma unroll
        for (int off = 1; off < 4; off <<= 1) {
            rmax0 = fmaxf(rmax0, __shfl_xor_sync(0xffffffffu, rmax0, off));
            rmax1 = fmaxf(rmax1, __shfl_xor_sync(0xffffffffu, rmax1, off));
        }
        const float mnew0 = fmaxf(mrow0, rmax0);
        const float mnew1 = fmaxf(mrow1, rmax1);
        const float alpha0 = __expf(mrow0 - mnew0);
        const float alpha1 = __expf(mrow1 - mnew1);
        float rs0 = 0.0f, rs1 = 0.0f;
#pragma unroll
        for (int ni = 0; ni < 8; ni++) {
            p0[ni][0] = __expf(p0[ni][0] - mnew0);
            p0[ni][1] = __expf(p0[ni][1] - mnew0);
            p1[ni][0] = __expf(p1[ni][0] - mnew1);
            p1[ni][1] = __expf(p1[ni][1] - mnew1);
            rs0 += p0[ni][0] + p0[ni][1];
            rs1 += p1[ni][0] + p1[ni][1];
        }
#pragma unroll
        for (int off = 1; off < 4; off <<= 1) {
            rs0 += __shfl_xor_sync(0xffffffffu, rs0, off);
            rs1 += __shfl_xor_sync(0xffffffffu, rs1, off);
        }
        lrow0 = lrow0 * alpha0 + rs0;
        lrow1 = lrow1 * alpha1 + rs1;
        mrow0 = mnew0;
        mrow1 = mnew1;
#pragma unroll
        for (int ni = 0; ni < 8; ni++) {
            Oacc[ni][0] *= alpha0; Oacc[ni][1] *= alpha0;
            Oacc[ni][2] *= alpha1; Oacc[ni][3] *= alpha1;
        }

        // ---- stash P (tf32) into this warp's private rows of Pf ----
        const int qr0 = wid * 16 + g;
#pragma unroll
        for (int ni = 0; ni < 8; ni++) {
            const int c = ni * 8 + 2 * tq;
            uint2 s0 = make_uint2(f2tf32(p0[ni][0]), f2tf32(p0[ni][1]));
            uint2 s1 = make_uint2(f2tf32(p1[ni][0]), f2tf32(p1[ni][1]));
            *(uint2*)(Pf + (qr0)     * PFP + c) = s0;
            *(uint2*)(Pf + (qr0 + 8) * PFP + c) = s1;
        }
        __syncwarp();

        // ---- O += P V : tf32 mma (unchanged from round 11) ----
#pragma unroll
        for (int ks = 0; ks < 8; ks++) {
            const int kk = ks * 8;
            uint32_t a0 = Pf[(mb + g)     * PFP + kk + tq];
            uint32_t a1 = Pf[(mb + g + 8) * PFP + kk + tq];
            uint32_t a2 = Pf[(mb + g)     * PFP + kk + tq + 4];
            uint32_t a3 = Pf[(mb + g + 8) * PFP + kk + tq + 4];
#pragma unroll
            for (int ni = 0; ni < 8; ni++) {
                const int nb = ni * 8;
                uint32_t b0 = Vs[(kk + tq)     * VFP + nb + g];
                uint32_t b1 = Vs[(kk + tq + 4) * VFP + nb + g];
                mma_tf32(Oacc[ni], a0, a1, a2, a3, b0, b1);
            }
        }
    }

    // ---- epilogue ----
    const float inv0 = 1.0f / lrow0;
    const float inv1 = 1.0f / lrow1;
    float* obase = out + (size_t)b * Sq * Dq + (size_t)h * HDq;
#pragma unroll
    for (int ni = 0; ni < 8; ni++) {
        const int c = ni * 8 + 2 * tq;
        float2 o0 = make_float2(Oacc[ni][0] * inv0, Oacc[ni][1] * inv0);
        float2 o1 = make_float2(Oacc[ni][2] * inv1, Oacc[ni][3] * inv1);
        *(float2*)(obase + (size_t)(q0 + r0) * Dq + c) = o0;
        *(float2*)(obase + (size_t)(q0 + r1) * Dq + c) = o1;
    }
}

// ---------------------------------------------------------------------------
extern "C" void kernel_launch(void* const* d_in, const int* in_sizes, int n_in,
                              void* d_out, int out_size)
{
    const float* x    = (const float*)d_in[0];
    const float* mask = (const float*)d_in[1];
    const float* Wqkv = (const float*)d_in[2];
    const float* bqkv = (const float*)d_in[3];
    const float* Wo   = (const float*)d_in[4];
    const float* bo   = (const float*)d_in[5];
    float* out = (float*)d_out;

    float*  qkv  = nullptr;
    float*  vals = nullptr;
    __half* qkh  = nullptr;
    cudaGetSymbolAddress((void**)&qkv,  g_qkv);
    cudaGetSymbolAddress((void**)&vals, g_vals);
    cudaGetSymbolAddress((void**)&qkh,  g_qkh);

    // 1) QKV projection: q/k -> fp16 qkh; v -> tf32-rounded g_qkv
    {
        dim3 grid((3 * Dq) / 128, (Bq * Sq) / 128);
        gemm_tf32_nt_bias<1><<<grid, 256>>>(Bq * Sq, 3 * Dq, Dq,
                                            x, Wqkv, bqkv, qkv, qkh);
    }

    // 2) Flash attention (fp16 S-phase, tf32 PV, 4 CTAs/SM, 2 barriers/tile)
    {
        cudaFuncSetAttribute(flash_attn_f16s,
                             cudaFuncAttributeMaxDynamicSharedMemorySize, FL_SMEM);
        dim3 grid(Sq / 64, Hq, Bq);
        flash_attn_f16s<<<grid, 128, FL_SMEM>>>(qkh, qkv, mask, vals);
    }

    // 3) Output projection (plain fp32 epilogue)
    {
        dim3 grid(Dq / 128, (Bq * Sq) / 128);
        gemm_tf32_nt_bias<0><<<grid, 256>>>(Bq * Sq, Dq, Dq,
                                            vals, Wo, bo, out, nullptr);
    }
}